// round 3
// baseline (speedup 1.0000x reference)
#include <cuda_runtime.h>

#define NN    8192
#define KIN   512
#define OUTF  64
#define ALPHA 0.2f
#define RTILE 32      // rows per CTA in k_fused
#define JT    64      // j-tile
#define NJT   (NN / JT)

typedef unsigned long long ull;

// ---------------- device scratch ----------------
__device__ float g_h[NN * OUTF];
__device__ float g_attl[NN];
__device__ float g_B[NN];     // exp(att_r)
__device__ float g_B2[NN];    // exp(ALPHA*att_r)
__device__ int   g_maxR;

// ---------------- helpers ----------------
__device__ __forceinline__ ull fma2(ull a, ull b, ull c) {
    ull d;
    asm("fma.rn.f32x2 %0, %1, %2, %3;" : "=l"(d) : "l"(a), "l"(b), "l"(c));
    return d;
}
__device__ __forceinline__ ull pack2(float x, float y) {
    ull d;
    asm("mov.b64 %0, {%1, %2};" : "=l"(d) : "f"(x), "f"(y));
    return d;
}
__device__ __forceinline__ ull dup2(float v) {
    ull d;
    asm("mov.b64 %0, {%1, %1};" : "=l"(d) : "f"(v));
    return d;
}
__device__ __forceinline__ int enc_f(float f) {
    int i = __float_as_int(f);
    return (i >= 0) ? i : (i ^ 0x7fffffff);
}
__device__ __forceinline__ float dec_f(int i) {
    int j = (i >= 0) ? i : (i ^ 0x7fffffff);
    return __int_as_float(j);
}
union F4U { float4 f; ull u[2]; };
union U64F2 { ull u; float2 f; };

// ---------------- kernel 0: reset global max ----------------
__global__ void k_init() { g_maxR = (int)0x80000000; }

// ---------------- kernel 1: h = input @ W ----------------
__global__ __launch_bounds__(256) void k_gemm(const float* __restrict__ input,
                                              const float* __restrict__ W) {
    __shared__ float in_s[64][68];
    __shared__ float w_s[64][64];

    const int tid = threadIdx.x;
    const int i0 = blockIdx.x * 64;
    const int rg = tid >> 4;
    const int cg = tid & 15;

    ull acc[4][2];
#pragma unroll
    for (int r = 0; r < 4; r++) { acc[r][0] = 0ull; acc[r][1] = 0ull; }

    for (int kc = 0; kc < KIN; kc += 64) {
        __syncthreads();
#pragma unroll
        for (int m = 0; m < 4; m++) {
            int idx = tid + 256 * m;
            int r = idx >> 4, k4 = (idx & 15) * 4;
            *(float4*)&in_s[r][k4] = *(const float4*)&input[(i0 + r) * KIN + kc + k4];
        }
#pragma unroll
        for (int m = 0; m < 4; m++) {
            int idx = tid + 256 * m;
            int k = idx >> 4, c4 = (idx & 15) * 4;
            *(float4*)&w_s[k][c4] = *(const float4*)&W[(kc + k) * OUTF + c4];
        }
        __syncthreads();

#pragma unroll 8
        for (int k = 0; k < 64; k++) {
            float4 wv = *(float4*)&w_s[k][cg * 4];
            ull wp0 = pack2(wv.x, wv.y);
            ull wp1 = pack2(wv.z, wv.w);
#pragma unroll
            for (int rr = 0; rr < 4; rr++) {
                ull vd = dup2(in_s[rg * 4 + rr][k]);
                acc[rr][0] = fma2(vd, wp0, acc[rr][0]);
                acc[rr][1] = fma2(vd, wp1, acc[rr][1]);
            }
        }
    }

#pragma unroll
    for (int rr = 0; rr < 4; rr++) {
        U64F2 a0, a1; a0.u = acc[rr][0]; a1.u = acc[rr][1];
        *(float4*)&g_h[(i0 + rg * 4 + rr) * OUTF + cg * 4] =
            make_float4(a0.f.x, a0.f.y, a1.f.x, a1.f.y);
    }
}

// ---------------- kernel 2: att_l, B=exp(att_r), B2=exp(a*att_r), max ----------------
__global__ __launch_bounds__(256) void k_att(const float* __restrict__ a) {
    const int w = threadIdx.x >> 5, lane = threadIdx.x & 31;
    const int row = blockIdx.x * 8 + w;
    float h0 = g_h[row * OUTF + lane];
    float h1 = g_h[row * OUTF + 32 + lane];
    float al = h0 * a[lane] + h1 * a[lane + 32];
    float ar = h0 * a[64 + lane] + h1 * a[96 + lane];
#pragma unroll
    for (int off = 16; off; off >>= 1) {
        al += __shfl_down_sync(0xffffffffu, al, off);
        ar += __shfl_down_sync(0xffffffffu, ar, off);
    }
    if (lane == 0) {
        g_attl[row] = al;
        g_B[row]  = __expf(ar);
        g_B2[row] = __expf(ALPHA * ar);
        atomicMax(&g_maxR, enc_f(ar));
    }
}

// ---------------- kernel 3: fused masked-softmax aggregation + ELU ----------------
// grid 256 CTAs x 128 threads, tile 32 rows x 64 cols, per-lane 2r x 8c.
__global__ __launch_bounds__(128, 3) void k_fused(const int* __restrict__ adj,
                                                  float* __restrict__ out) {
    __shared__ float4 h_s[JT * OUTF / 4];     // 16 KB   h tile [j][c]
    __shared__ ull    w2_s[RTILE * 66];       // 16.5 KB dup weight pairs, 66-pair rows
    __shared__ float  Z_s[RTILE];

    const int tid = threadIdx.x;
    const int i0 = blockIdx.x * RTILE;

    // phase-A identity: 4 threads per row, 16 j's each
    const int arow = tid >> 2;
    const int ajo  = (tid & 3) * 16;
    // phase-B identity: warp tile 8r x 64c; lane = 2 rows x 8 cols
    const int lane = tid & 31, wrp = tid >> 5;
    const int rg = lane >> 3, cg = lane & 7;
    const int r0 = wrp * 8 + rg * 2, r1 = r0 + 1;

    // per-row constants (rank-1 factors)
    const float mr = dec_f(g_maxR);
    const float al = g_attl[i0 + arow];
    const float sC = al + mr;
    const float C  = fmaxf(sC, ALPHA * sC);
    const float Aw  = __expf(al - C);
    const float A2w = __expf(ALPHA * al - C);

    float Zacc = 0.f;
    ull acc[2][4];
#pragma unroll
    for (int r = 0; r < 2; r++)
#pragma unroll
        for (int c = 0; c < 4; c++) acc[r][c] = 0ull;

    const ull* wrow0 = &w2_s[r0 * 66];
    const ull* wrow1 = &w2_s[r1 * 66];
    ull* wst = &w2_s[arow * 66 + ajo];

    for (int jt = 0; jt < NJT; jt++) {
        const int j0 = jt * JT;
        __syncthreads();

        // ---- load h tile (16 KB, fully coalesced) ----
        {
            const float4* hs = (const float4*)(g_h + j0 * OUTF);
#pragma unroll
            for (int k = 0; k < 8; k++) h_s[tid + 128 * k] = hs[tid + 128 * k];
        }

        // ---- phase A: w[row][j] = adj ? max(A*B, A2*B2) : 0, store dup pairs ----
        {
            const int4* ap = (const int4*)&adj[(i0 + arow) * NN + j0 + ajo];
            int4 m0 = ap[0], m1 = ap[1], m2 = ap[2], m3 = ap[3];
            const float4* Bp  = (const float4*)&g_B[j0 + ajo];
            const float4* B2p = (const float4*)&g_B2[j0 + ajo];
            float w[16];
#pragma unroll
            for (int q = 0; q < 4; q++) {
                float4 b = Bp[q], b2 = B2p[q];
                int4 m = (q == 0) ? m0 : (q == 1) ? m1 : (q == 2) ? m2 : m3;
                float v0 = fmaxf(Aw * b.x, A2w * b2.x);
                float v1 = fmaxf(Aw * b.y, A2w * b2.y);
                float v2 = fmaxf(Aw * b.z, A2w * b2.z);
                float v3 = fmaxf(Aw * b.w, A2w * b2.w);
                w[q * 4 + 0] = m.x ? v0 : 0.f;
                w[q * 4 + 1] = m.y ? v1 : 0.f;
                w[q * 4 + 2] = m.z ? v2 : 0.f;
                w[q * 4 + 3] = m.w ? v3 : 0.f;
            }
#pragma unroll
            for (int k = 0; k < 16; k++) Zacc += w[k];
#pragma unroll
            for (int p = 0; p < 8; p++) {
                F4U d;
                d.f = make_float4(w[2 * p], w[2 * p], w[2 * p + 1], w[2 * p + 1]);
                *(float4*)&wst[2 * p] = d.f;
            }
        }
        __syncthreads();

        // ---- phase B: acc[2r x 8c] += w[2 x JT] * h[JT x 8c] ----
#pragma unroll 4
        for (int j4 = 0; j4 < JT; j4 += 4) {
            ulonglong2 wa01 = *(const ulonglong2*)&wrow0[j4];
            ulonglong2 wa23 = *(const ulonglong2*)&wrow0[j4 + 2];
            ulonglong2 wb01 = *(const ulonglong2*)&wrow1[j4];
            ulonglong2 wb23 = *(const ulonglong2*)&wrow1[j4 + 2];
            ull wa[4] = {wa01.x, wa01.y, wa23.x, wa23.y};
            ull wb[4] = {wb01.x, wb01.y, wb23.x, wb23.y};
#pragma unroll
            for (int jj = 0; jj < 4; jj++) {
                F4U h0, h1;
                h0.f = h_s[(j4 + jj) * 16 + cg * 2];
                h1.f = h_s[(j4 + jj) * 16 + cg * 2 + 1];
                acc[0][0] = fma2(wa[jj], h0.u[0], acc[0][0]);
                acc[0][1] = fma2(wa[jj], h0.u[1], acc[0][1]);
                acc[0][2] = fma2(wa[jj], h1.u[0], acc[0][2]);
                acc[0][3] = fma2(wa[jj], h1.u[1], acc[0][3]);
                acc[1][0] = fma2(wb[jj], h0.u[0], acc[1][0]);
                acc[1][1] = fma2(wb[jj], h0.u[1], acc[1][1]);
                acc[1][2] = fma2(wb[jj], h1.u[0], acc[1][2]);
                acc[1][3] = fma2(wb[jj], h1.u[1], acc[1][3]);
            }
        }
    }

    // ---- Z reduce (4 lanes per row) ----
    Zacc += __shfl_xor_sync(0xffffffffu, Zacc, 1);
    Zacc += __shfl_xor_sync(0xffffffffu, Zacc, 2);
    if ((tid & 3) == 0) Z_s[arow] = Zacc;
    __syncthreads();

    // ---- normalize + ELU + store ----
#pragma unroll
    for (int rr = 0; rr < 2; rr++) {
        const int r = rr ? r1 : r0;
        const float inv = 1.0f / Z_s[r];
        float v[8];
#pragma unroll
        for (int c = 0; c < 4; c++) {
            U64F2 a; a.u = acc[rr][c];
            v[2 * c]     = a.f.x * inv;
            v[2 * c + 1] = a.f.y * inv;
        }
#pragma unroll
        for (int k = 0; k < 8; k++) v[k] = (v[k] > 0.f) ? v[k] : expm1f(v[k]);
        float* op = &out[(i0 + r) * OUTF + cg * 8];
        *(float4*)op       = make_float4(v[0], v[1], v[2], v[3]);
        *(float4*)(op + 4) = make_float4(v[4], v[5], v[6], v[7]);
    }
}

// ---------------- launch ----------------
extern "C" void kernel_launch(void* const* d_in, const int* in_sizes, int n_in,
                              void* d_out, int out_size) {
    const float* input = (const float*)d_in[0];   // [8192, 512]
    const int*   adj   = (const int*)d_in[1];     // [8192, 8192]
    const float* W     = (const float*)d_in[2];   // [512, 64]
    const float* a     = (const float*)d_in[3];   // [128, 1]
    float* out = (float*)d_out;                   // [8192, 64]

    k_init<<<1, 1>>>();
    k_gemm<<<NN / 64, 256>>>(input, W);
    k_att<<<NN / 8, 256>>>(a);
    k_fused<<<NN / RTILE, 128>>>(adj, out);
}

// round 6
// speedup vs baseline: 2.7268x; 2.7268x over previous
#include <cuda_runtime.h>
#include <cuda_fp16.h>
#include <cstdint>

#define NN    8192
#define KIN   512
#define OUTF  64
#define ALPHA 0.2f
#define JSPAN 4096
#define NTILE (JSPAN / 16)    // 256 j-tiles per CTA

typedef unsigned long long ull;
typedef unsigned int u32;

// ---------------- device scratch ----------------
__device__ float g_h[NN * OUTF];                  // fp32 h
__device__ float g_attl[NN];
__device__ float g_B[NN];                         // exp(att_r)
__device__ float g_B2[NN];                        // exp(ALPHA*att_r)
__device__ int   g_maxR;
__device__ uint4 g_bfrag[(NN / 16) * 4 * 32];     // B fragments: [jt][np][lane], 1 MB
__device__ float g_part[2][NN * OUTF];            // per-split partials
__device__ float g_Zp[2][NN];                     // per-split Z

// ---------------- helpers ----------------
__device__ __forceinline__ ull fma2(ull a, ull b, ull c) {
    ull d; asm("fma.rn.f32x2 %0, %1, %2, %3;" : "=l"(d) : "l"(a), "l"(b), "l"(c)); return d;
}
__device__ __forceinline__ ull pack2(float x, float y) {
    ull d; asm("mov.b64 %0, {%1, %2};" : "=l"(d) : "f"(x), "f"(y)); return d;
}
__device__ __forceinline__ ull dup2(float v) {
    ull d; asm("mov.b64 %0, {%1, %1};" : "=l"(d) : "f"(v)); return d;
}
__device__ __forceinline__ u32 cvt2h(float lo, float hi) {   // lo -> lower half
    u32 d; asm("cvt.rn.f16x2.f32 %0, %1, %2;" : "=r"(d) : "f"(hi), "f"(lo)); return d;
}
__device__ __forceinline__ int enc_f(float f) {
    int i = __float_as_int(f); return (i >= 0) ? i : (i ^ 0x7fffffff);
}
__device__ __forceinline__ float dec_f(int i) {
    int j = (i >= 0) ? i : (i ^ 0x7fffffff); return __int_as_float(j);
}
__device__ __forceinline__ void mma16816(float* d, u32 a0, u32 a1, u32 a2, u32 a3,
                                         u32 b0, u32 b1) {
    asm("mma.sync.aligned.m16n8k16.row.col.f32.f16.f16.f32 "
        "{%0,%1,%2,%3}, {%4,%5,%6,%7}, {%8,%9}, {%0,%1,%2,%3};"
        : "+f"(d[0]), "+f"(d[1]), "+f"(d[2]), "+f"(d[3])
        : "r"(a0), "r"(a1), "r"(a2), "r"(a3), "r"(b0), "r"(b1));
}
union U64F2 { ull u; float2 f; };

// ---------------- kernel 0: reset global max ----------------
__global__ void k_init() { g_maxR = (int)0x80000000; }

// ---------------- kernel 1: h = input @ W (fp32, FFMA2 tiled) ----------------
__global__ __launch_bounds__(256) void k_gemm(const float* __restrict__ input,
                                              const float* __restrict__ W) {
    __shared__ float in_s[64][68];
    __shared__ float w_s[64][64];

    const int tid = threadIdx.x;
    const int i0 = blockIdx.x * 64;
    const int rg = tid >> 4;
    const int cg = tid & 15;

    ull acc[4][2];
#pragma unroll
    for (int r = 0; r < 4; r++) { acc[r][0] = 0ull; acc[r][1] = 0ull; }

    for (int kc = 0; kc < KIN; kc += 64) {
        __syncthreads();
#pragma unroll
        for (int m = 0; m < 4; m++) {
            int idx = tid + 256 * m;
            int r = idx >> 4, k4 = (idx & 15) * 4;
            *(float4*)&in_s[r][k4] = *(const float4*)&input[(i0 + r) * KIN + kc + k4];
        }
#pragma unroll
        for (int m = 0; m < 4; m++) {
            int idx = tid + 256 * m;
            int k = idx >> 4, c4 = (idx & 15) * 4;
            *(float4*)&w_s[k][c4] = *(const float4*)&W[(kc + k) * OUTF + c4];
        }
        __syncthreads();

#pragma unroll 8
        for (int k = 0; k < 64; k++) {
            float4 wv = *(float4*)&w_s[k][cg * 4];
            ull wp0 = pack2(wv.x, wv.y);
            ull wp1 = pack2(wv.z, wv.w);
#pragma unroll
            for (int rr = 0; rr < 4; rr++) {
                ull vd = dup2(in_s[rg * 4 + rr][k]);
                acc[rr][0] = fma2(vd, wp0, acc[rr][0]);
                acc[rr][1] = fma2(vd, wp1, acc[rr][1]);
            }
        }
    }

#pragma unroll
    for (int rr = 0; rr < 4; rr++) {
        U64F2 a0, a1; a0.u = acc[rr][0]; a1.u = acc[rr][1];
        *(float4*)&g_h[(i0 + rg * 4 + rr) * OUTF + cg * 4] =
            make_float4(a0.f.x, a0.f.y, a1.f.x, a1.f.y);
    }
}

// ---------------- kernel 2: att factors ----------------
__global__ __launch_bounds__(256) void k_att(const float* __restrict__ a) {
    const int w = threadIdx.x >> 5, lane = threadIdx.x & 31;
    const int row = blockIdx.x * 8 + w;
    float h0 = g_h[row * OUTF + lane];
    float h1 = g_h[row * OUTF + 32 + lane];
    float al = h0 * a[lane] + h1 * a[lane + 32];
    float ar = h0 * a[64 + lane] + h1 * a[96 + lane];
#pragma unroll
    for (int off = 16; off; off >>= 1) {
        al += __shfl_down_sync(0xffffffffu, al, off);
        ar += __shfl_down_sync(0xffffffffu, ar, off);
    }
    if (lane == 0) {
        g_attl[row] = al;
        g_B[row]  = __expf(ar);
        g_B2[row] = __expf(ALPHA * ar);
        atomicMax(&g_maxR, enc_f(ar));
    }
}

// ---------------- kernel 3: build B fragments (h -> fp16 mma layout) ----------
// Layout per (jt, np, lane(g,t)):
//   .x = pack(h[16jt+4t+0][16np+g],   h[16jt+4t+1][16np+g])
//   .y = pack(h[16jt+4t+2][16np+g],   h[16jt+4t+3][16np+g])
//   .z,.w = same with col 16np+8+g
__global__ __launch_bounds__(256) void k_prep() {
    int idx = blockIdx.x * 256 + threadIdx.x;      // 65536 threads
    int l = idx & 31, np = (idx >> 5) & 3, jt = idx >> 7;
    int g = l >> 2, t = l & 3;
    int j0 = jt * 16 + t * 4;
    int c0 = np * 16 + g, c1 = c0 + 8;
    const float* h = g_h;
    uint4 v;
    v.x = cvt2h(h[(j0 + 0) * OUTF + c0], h[(j0 + 1) * OUTF + c0]);
    v.y = cvt2h(h[(j0 + 2) * OUTF + c0], h[(j0 + 3) * OUTF + c0]);
    v.z = cvt2h(h[(j0 + 0) * OUTF + c1], h[(j0 + 1) * OUTF + c1]);
    v.w = cvt2h(h[(j0 + 2) * OUTF + c1], h[(j0 + 3) * OUTF + c1]);
    g_bfrag[idx] = v;
}

// ---------------- kernel 4: fused weight-gen + HMMA aggregation ---------------
// grid 128 = 64 i-tiles (128 rows) x 2 j-splits. 8 warps; warp = 16 rows x 64 cols.
// No smem, no __syncthreads.
__global__ __launch_bounds__(256) void k_fused(const int* __restrict__ adj) {
    const int tid = threadIdx.x;
    const int w = tid >> 5, l = tid & 31;
    const int g = l >> 2, t = l & 3;
    const int itile = blockIdx.x >> 1, split = blockIdx.x & 1;
    const int i0 = itile * 128;
    const int jb = split * JSPAN;
    const int row0 = i0 + w * 16 + g, row1 = row0 + 8;

    // per-row rank-1 factors
    const float mr = dec_f(g_maxR);
    const float al0 = g_attl[row0], al1 = g_attl[row1];
    const float s0 = al0 + mr, s1 = al1 + mr;
    const float C0 = fmaxf(s0, ALPHA * s0), C1 = fmaxf(s1, ALPHA * s1);
    const float Aw0 = __expf(al0 - C0), A2w0 = __expf(ALPHA * al0 - C0);
    const float Aw1 = __expf(al1 - C1), A2w1 = __expf(ALPHA * al1 - C1);

    float acc[8][4];
#pragma unroll
    for (int n = 0; n < 8; n++)
#pragma unroll
        for (int c = 0; c < 4; c++) acc[n][c] = 0.f;
    float Z0 = 0.f, Z1 = 0.f;

    const int4*   ap0 = (const int4*)(adj + (size_t)row0 * NN + jb) + t;
    const int4*   ap1 = (const int4*)(adj + (size_t)row1 * NN + jb) + t;
    const float4* Bp  = (const float4*)(g_B + jb) + t;
    const float4* B2p = (const float4*)(g_B2 + jb) + t;
    const uint4*  bfp = g_bfrag + (jb / 16) * 128 + l;

#pragma unroll 2
    for (int tt = 0; tt < NTILE; tt++) {
        const int4 m0 = ap0[4 * tt];
        const int4 m1 = ap1[4 * tt];
        const float4 b  = Bp[4 * tt];
        const float4 b2 = B2p[4 * tt];

        // A fragment: a0=(row0, j 4t..4t+1) a1=(row1, same) a2=(row0, 4t+2..3) a3=(row1, ...)
        u32 a0, a1, a2, a3;
        {
            float p0 = fmaxf(Aw0 * b.x, A2w0 * b2.x);
            float p1 = fmaxf(Aw0 * b.y, A2w0 * b2.y);
            float p2 = fmaxf(Aw0 * b.z, A2w0 * b2.z);
            float p3 = fmaxf(Aw0 * b.w, A2w0 * b2.w);
            u32 k01 = (u32)m0.x * 0xFFFFu + (u32)m0.y * 0xFFFF0000u;
            u32 k23 = (u32)m0.z * 0xFFFFu + (u32)m0.w * 0xFFFF0000u;
            a0 = cvt2h(p0, p1) & k01;
            a2 = cvt2h(p2, p3) & k23;
            __half2 hs = __hadd2(*(__half2*)&a0, *(__half2*)&a2);
            Z0 += __low2float(hs) + __high2float(hs);
        }
        {
            float p0 = fmaxf(Aw1 * b.x, A2w1 * b2.x);
            float p1 = fmaxf(Aw1 * b.y, A2w1 * b2.y);
            float p2 = fmaxf(Aw1 * b.z, A2w1 * b2.z);
            float p3 = fmaxf(Aw1 * b.w, A2w1 * b2.w);
            u32 k01 = (u32)m1.x * 0xFFFFu + (u32)m1.y * 0xFFFF0000u;
            u32 k23 = (u32)m1.z * 0xFFFFu + (u32)m1.w * 0xFFFF0000u;
            a1 = cvt2h(p0, p1) & k01;
            a3 = cvt2h(p2, p3) & k23;
            __half2 hs = __hadd2(*(__half2*)&a1, *(__half2*)&a3);
            Z1 += __low2float(hs) + __high2float(hs);
        }

        const uint4* bf = bfp + tt * 128;
#pragma unroll
        for (int np = 0; np < 4; np++) {
            uint4 bb = bf[np * 32];
            mma16816(acc[2 * np],     a0, a1, a2, a3, bb.x, bb.y);
            mma16816(acc[2 * np + 1], a0, a1, a2, a3, bb.z, bb.w);
        }
    }

    // ---- store partials: c0,c1 -> row0 cols (8nt+2t, +1); c2,c3 -> row1 ----
    float* p0g = &g_part[split][(size_t)row0 * OUTF];
    float* p1g = &g_part[split][(size_t)row1 * OUTF];
#pragma unroll
    for (int nt = 0; nt < 8; nt++) {
        int col = nt * 8 + 2 * t;
        *(float2*)&p0g[col] = make_float2(acc[nt][0], acc[nt][1]);
        *(float2*)&p1g[col] = make_float2(acc[nt][2], acc[nt][3]);
    }

    // ---- Z reduce across the 4 t-lanes of each row ----
    Z0 += __shfl_xor_sync(0xffffffffu, Z0, 1);
    Z0 += __shfl_xor_sync(0xffffffffu, Z0, 2);
    Z1 += __shfl_xor_sync(0xffffffffu, Z1, 1);
    Z1 += __shfl_xor_sync(0xffffffffu, Z1, 2);
    if (t == 0) {
        g_Zp[split][row0] = Z0;
        g_Zp[split][row1] = Z1;
    }
}

// ---------------- kernel 5: combine splits, normalize, ELU ----------------
__global__ __launch_bounds__(256) void k_red(float* __restrict__ out) {
    int idx = blockIdx.x * 256 + threadIdx.x;   // float4 index, 131072 total
    int row = idx >> 4;
    float4 p0 = ((const float4*)g_part[0])[idx];
    float4 p1 = ((const float4*)g_part[1])[idx];
    float inv = 1.0f / (g_Zp[0][row] + g_Zp[1][row]);
    float v0 = (p0.x + p1.x) * inv;
    float v1 = (p0.y + p1.y) * inv;
    float v2 = (p0.z + p1.z) * inv;
    float v3 = (p0.w + p1.w) * inv;
    v0 = (v0 > 0.f) ? v0 : expm1f(v0);
    v1 = (v1 > 0.f) ? v1 : expm1f(v1);
    v2 = (v2 > 0.f) ? v2 : expm1f(v2);
    v3 = (v3 > 0.f) ? v3 : expm1f(v3);
    ((float4*)out)[idx] = make_float4(v0, v1, v2, v3);
}

// ---------------- launch ----------------
extern "C" void kernel_launch(void* const* d_in, const int* in_sizes, int n_in,
                              void* d_out, int out_size) {
    const float* input = (const float*)d_in[0];   // [8192, 512]
    const int*   adj   = (const int*)d_in[1];     // [8192, 8192]
    const float* W     = (const float*)d_in[2];   // [512, 64]
    const float* a     = (const float*)d_in[3];   // [128, 1]
    float* out = (float*)d_out;                   // [8192, 64]

    k_init<<<1, 1>>>();
    k_gemm<<<NN / 64, 256>>>(input, W);
    k_att<<<NN / 8, 256>>>(a);
    k_prep<<<256, 256>>>();
    k_fused<<<128, 256>>>(adj);
    k_red<<<512, 256>>>(out);
}

// round 7
// speedup vs baseline: 7.5356x; 2.7635x over previous
#include <cuda_runtime.h>
#include <cuda_fp16.h>
#include <cstdint>

#define NN    8192
#define KIN   512
#define OUTF  64
#define ALPHA 0.2f
#define NSPLIT 8
#define JSPAN (NN / NSPLIT)       // 1024
#define NTILE (JSPAN / 16)        // 64 j-tiles per CTA

typedef unsigned long long ull;
typedef unsigned int u32;

// ---------------- device scratch ----------------
__device__ float g_h[NN * OUTF];                  // fp32 h
__device__ float g_attl[NN];
__device__ float g_B[NN];                         // exp(att_r)
__device__ float g_B2[NN];                        // exp(ALPHA*att_r)
__device__ int   g_maxR;
__device__ uint4 g_bfrag[(NN / 16) * 4 * 32];     // B fragments: [jt][np][lane], 1 MB
__device__ float g_part[NSPLIT][NN * OUTF];       // per-split partials (16 MB)
__device__ float g_Zp[NSPLIT][NN];                // per-split Z

// ---------------- helpers ----------------
__device__ __forceinline__ ull fma2(ull a, ull b, ull c) {
    ull d; asm("fma.rn.f32x2 %0, %1, %2, %3;" : "=l"(d) : "l"(a), "l"(b), "l"(c)); return d;
}
__device__ __forceinline__ ull pack2(float x, float y) {
    ull d; asm("mov.b64 %0, {%1, %2};" : "=l"(d) : "f"(x), "f"(y)); return d;
}
__device__ __forceinline__ ull dup2(float v) {
    ull d; asm("mov.b64 %0, {%1, %1};" : "=l"(d) : "f"(v)); return d;
}
__device__ __forceinline__ u32 cvt2h(float lo, float hi) {   // lo -> lower half
    u32 d; asm("cvt.rn.f16x2.f32 %0, %1, %2;" : "=r"(d) : "f"(hi), "f"(lo)); return d;
}
__device__ __forceinline__ int enc_f(float f) {
    int i = __float_as_int(f); return (i >= 0) ? i : (i ^ 0x7fffffff);
}
__device__ __forceinline__ float dec_f(int i) {
    int j = (i >= 0) ? i : (i ^ 0x7fffffff); return __int_as_float(j);
}
__device__ __forceinline__ void mma16816(float* d, u32 a0, u32 a1, u32 a2, u32 a3,
                                         u32 b0, u32 b1) {
    asm("mma.sync.aligned.m16n8k16.row.col.f32.f16.f16.f32 "
        "{%0,%1,%2,%3}, {%4,%5,%6,%7}, {%8,%9}, {%0,%1,%2,%3};"
        : "+f"(d[0]), "+f"(d[1]), "+f"(d[2]), "+f"(d[3])
        : "r"(a0), "r"(a1), "r"(a2), "r"(a3), "r"(b0), "r"(b1));
}
union U64F2 { ull u; float2 f; };

// ---------------- kernel 0: reset global max ----------------
__global__ void k_init() { g_maxR = (int)0x80000000; }

// ---------------- kernel 1: h = input @ W (fp32, FFMA2 tiled) ----------------
__global__ __launch_bounds__(256) void k_gemm(const float* __restrict__ input,
                                              const float* __restrict__ W) {
    __shared__ float in_s[64][68];
    __shared__ float w_s[64][64];

    const int tid = threadIdx.x;
    const int i0 = blockIdx.x * 64;
    const int rg = tid >> 4;
    const int cg = tid & 15;

    ull acc[4][2];
#pragma unroll
    for (int r = 0; r < 4; r++) { acc[r][0] = 0ull; acc[r][1] = 0ull; }

    for (int kc = 0; kc < KIN; kc += 64) {
        __syncthreads();
#pragma unroll
        for (int m = 0; m < 4; m++) {
            int idx = tid + 256 * m;
            int r = idx >> 4, k4 = (idx & 15) * 4;
            *(float4*)&in_s[r][k4] = *(const float4*)&input[(i0 + r) * KIN + kc + k4];
        }
#pragma unroll
        for (int m = 0; m < 4; m++) {
            int idx = tid + 256 * m;
            int k = idx >> 4, c4 = (idx & 15) * 4;
            *(float4*)&w_s[k][c4] = *(const float4*)&W[(kc + k) * OUTF + c4];
        }
        __syncthreads();

#pragma unroll 8
        for (int k = 0; k < 64; k++) {
            float4 wv = *(float4*)&w_s[k][cg * 4];
            ull wp0 = pack2(wv.x, wv.y);
            ull wp1 = pack2(wv.z, wv.w);
#pragma unroll
            for (int rr = 0; rr < 4; rr++) {
                ull vd = dup2(in_s[rg * 4 + rr][k]);
                acc[rr][0] = fma2(vd, wp0, acc[rr][0]);
                acc[rr][1] = fma2(vd, wp1, acc[rr][1]);
            }
        }
    }

#pragma unroll
    for (int rr = 0; rr < 4; rr++) {
        U64F2 a0, a1; a0.u = acc[rr][0]; a1.u = acc[rr][1];
        *(float4*)&g_h[(i0 + rg * 4 + rr) * OUTF + cg * 4] =
            make_float4(a0.f.x, a0.f.y, a1.f.x, a1.f.y);
    }
}

// ---------------- kernel 2: att factors ----------------
__global__ __launch_bounds__(256) void k_att(const float* __restrict__ a) {
    const int w = threadIdx.x >> 5, lane = threadIdx.x & 31;
    const int row = blockIdx.x * 8 + w;
    float h0 = g_h[row * OUTF + lane];
    float h1 = g_h[row * OUTF + 32 + lane];
    float al = h0 * a[lane] + h1 * a[lane + 32];
    float ar = h0 * a[64 + lane] + h1 * a[96 + lane];
#pragma unroll
    for (int off = 16; off; off >>= 1) {
        al += __shfl_down_sync(0xffffffffu, al, off);
        ar += __shfl_down_sync(0xffffffffu, ar, off);
    }
    if (lane == 0) {
        g_attl[row] = al;
        g_B[row]  = __expf(ar);
        g_B2[row] = __expf(ALPHA * ar);
        atomicMax(&g_maxR, enc_f(ar));
    }
}

// ---------------- kernel 3: build B fragments (h -> fp16 mma layout) ----------
__global__ __launch_bounds__(256) void k_prep() {
    int idx = blockIdx.x * 256 + threadIdx.x;      // 65536 threads
    int l = idx & 31, np = (idx >> 5) & 3, jt = idx >> 7;
    int g = l >> 2, t = l & 3;
    int j0 = jt * 16 + t * 4;
    int c0 = np * 16 + g, c1 = c0 + 8;
    const float* h = g_h;
    uint4 v;
    v.x = cvt2h(h[(j0 + 0) * OUTF + c0], h[(j0 + 1) * OUTF + c0]);
    v.y = cvt2h(h[(j0 + 2) * OUTF + c0], h[(j0 + 3) * OUTF + c0]);
    v.z = cvt2h(h[(j0 + 0) * OUTF + c1], h[(j0 + 1) * OUTF + c1]);
    v.w = cvt2h(h[(j0 + 2) * OUTF + c1], h[(j0 + 3) * OUTF + c1]);
    g_bfrag[idx] = v;
}

// ---------------- kernel 4: fused weight-gen + HMMA aggregation ---------------
// grid 512 = 64 i-tiles (128 rows) x 8 j-splits (1024 j each). 8 warps/CTA,
// warp = 16 rows x 64 cols. No smem, no __syncthreads, >=2 CTAs/SM.
__global__ __launch_bounds__(256, 2) void k_fused(const int* __restrict__ adj) {
    const int tid = threadIdx.x;
    const int w = tid >> 5, l = tid & 31;
    const int g = l >> 2, t = l & 3;
    const int itile = blockIdx.x >> 3, split = blockIdx.x & 7;
    const int i0 = itile * 128;
    const int jb = split * JSPAN;
    const int row0 = i0 + w * 16 + g, row1 = row0 + 8;

    // per-row rank-1 factors
    const float mr = dec_f(g_maxR);
    const float al0 = g_attl[row0], al1 = g_attl[row1];
    const float s0 = al0 + mr, s1 = al1 + mr;
    const float C0 = fmaxf(s0, ALPHA * s0), C1 = fmaxf(s1, ALPHA * s1);
    const float Aw0 = __expf(al0 - C0), A2w0 = __expf(ALPHA * al0 - C0);
    const float Aw1 = __expf(al1 - C1), A2w1 = __expf(ALPHA * al1 - C1);

    float acc[8][4];
#pragma unroll
    for (int n = 0; n < 8; n++)
#pragma unroll
        for (int c = 0; c < 4; c++) acc[n][c] = 0.f;
    float Z0 = 0.f, Z1 = 0.f;

    const int4*   ap0 = (const int4*)(adj + (size_t)row0 * NN + jb) + t;
    const int4*   ap1 = (const int4*)(adj + (size_t)row1 * NN + jb) + t;
    const float4* Bp  = (const float4*)(g_B + jb) + t;
    const float4* B2p = (const float4*)(g_B2 + jb) + t;
    const uint4*  bfp = g_bfrag + (jb / 16) * 128 + l;

#pragma unroll 2
    for (int tt = 0; tt < NTILE; tt++) {
        const int4 m0 = ap0[4 * tt];
        const int4 m1 = ap1[4 * tt];
        const float4 b  = Bp[4 * tt];
        const float4 b2 = B2p[4 * tt];

        u32 a0, a1, a2, a3;
        {
            float p0 = fmaxf(Aw0 * b.x, A2w0 * b2.x);
            float p1 = fmaxf(Aw0 * b.y, A2w0 * b2.y);
            float p2 = fmaxf(Aw0 * b.z, A2w0 * b2.z);
            float p3 = fmaxf(Aw0 * b.w, A2w0 * b2.w);
            u32 k01 = (u32)m0.x * 0xFFFFu + (u32)m0.y * 0xFFFF0000u;
            u32 k23 = (u32)m0.z * 0xFFFFu + (u32)m0.w * 0xFFFF0000u;
            a0 = cvt2h(p0, p1) & k01;
            a2 = cvt2h(p2, p3) & k23;
            __half2 hs = __hadd2(*(__half2*)&a0, *(__half2*)&a2);
            Z0 += __low2float(hs) + __high2float(hs);
        }
        {
            float p0 = fmaxf(Aw1 * b.x, A2w1 * b2.x);
            float p1 = fmaxf(Aw1 * b.y, A2w1 * b2.y);
            float p2 = fmaxf(Aw1 * b.z, A2w1 * b2.z);
            float p3 = fmaxf(Aw1 * b.w, A2w1 * b2.w);
            u32 k01 = (u32)m1.x * 0xFFFFu + (u32)m1.y * 0xFFFF0000u;
            u32 k23 = (u32)m1.z * 0xFFFFu + (u32)m1.w * 0xFFFF0000u;
            a1 = cvt2h(p0, p1) & k01;
            a3 = cvt2h(p2, p3) & k23;
            __half2 hs = __hadd2(*(__half2*)&a1, *(__half2*)&a3);
            Z1 += __low2float(hs) + __high2float(hs);
        }

        const uint4* bf = bfp + tt * 128;
#pragma unroll
        for (int np = 0; np < 4; np++) {
            uint4 bb = bf[np * 32];
            mma16816(acc[2 * np],     a0, a1, a2, a3, bb.x, bb.y);
            mma16816(acc[2 * np + 1], a0, a1, a2, a3, bb.z, bb.w);
        }
    }

    // ---- store partials ----
    float* p0g = &g_part[split][(size_t)row0 * OUTF];
    float* p1g = &g_part[split][(size_t)row1 * OUTF];
#pragma unroll
    for (int nt = 0; nt < 8; nt++) {
        int col = nt * 8 + 2 * t;
        *(float2*)&p0g[col] = make_float2(acc[nt][0], acc[nt][1]);
        *(float2*)&p1g[col] = make_float2(acc[nt][2], acc[nt][3]);
    }

    // ---- Z reduce across the 4 t-lanes of each row ----
    Z0 += __shfl_xor_sync(0xffffffffu, Z0, 1);
    Z0 += __shfl_xor_sync(0xffffffffu, Z0, 2);
    Z1 += __shfl_xor_sync(0xffffffffu, Z1, 1);
    Z1 += __shfl_xor_sync(0xffffffffu, Z1, 2);
    if (t == 0) {
        g_Zp[split][row0] = Z0;
        g_Zp[split][row1] = Z1;
    }
}

// ---------------- kernel 5: combine splits, normalize, ELU ----------------
__global__ __launch_bounds__(256) void k_red(float* __restrict__ out) {
    int idx = blockIdx.x * 256 + threadIdx.x;   // float4 index, 131072 total
    int row = idx >> 4;
    float4 p = ((const float4*)g_part[0])[idx];
    float Z = g_Zp[0][row];
#pragma unroll
    for (int s = 1; s < NSPLIT; s++) {
        float4 q = ((const float4*)g_part[s])[idx];
        p.x += q.x; p.y += q.y; p.z += q.z; p.w += q.w;
        Z += g_Zp[s][row];
    }
    float inv = 1.0f / Z;
    float v0 = p.x * inv, v1 = p.y * inv, v2 = p.z * inv, v3 = p.w * inv;
    v0 = (v0 > 0.f) ? v0 : expm1f(v0);
    v1 = (v1 > 0.f) ? v1 : expm1f(v1);
    v2 = (v2 > 0.f) ? v2 : expm1f(v2);
    v3 = (v3 > 0.f) ? v3 : expm1f(v3);
    ((float4*)out)[idx] = make_float4(v0, v1, v2, v3);
}

// ---------------- launch ----------------
extern "C" void kernel_launch(void* const* d_in, const int* in_sizes, int n_in,
                              void* d_out, int out_size) {
    const float* input = (const float*)d_in[0];   // [8192, 512]
    const int*   adj   = (const int*)d_in[1];     // [8192, 8192]
    const float* W     = (const float*)d_in[2];   // [512, 64]
    const float* a     = (const float*)d_in[3];   // [128, 1]
    float* out = (float*)d_out;                   // [8192, 64]

    k_init<<<1, 1>>>();
    k_gemm<<<NN / 64, 256>>>(input, W);
    k_att<<<NN / 8, 256>>>(a);
    k_prep<<<256, 256>>>();
    k_fused<<<NN / 128 * NSPLIT, 256>>>(adj);
    k_red<<<512, 256>>>(out);
}